// round 1
// baseline (speedup 1.0000x reference)
#include <cuda_runtime.h>

#define N_NODES 4096
#define F_IN    512
#define H_HEADS 4
#define FO_DIM  128
#define C_OUT   512   // H_HEADS * FO_DIM

// Scratch (allocation-free rule: __device__ globals)
__device__ float g_feats[N_NODES * C_OUT];   // [n][h*128+o]  (node-major, 8 MB)
__device__ float g_es[N_NODES * H_HEADS];    // [n*4+h]
__device__ float g_en[N_NODES * H_HEADS];    // [n*4+h]

// ---------------------------------------------------------------------------
// Kernel 1: feats[n][c] = sum_f X[n][f] * W[c>>7][f][c&127]
// Classic SMEM-tiled fp32 GEMM, BM=BN=64, BK=16, 256 threads, 4x4 microtile.
// ---------------------------------------------------------------------------
__global__ __launch_bounds__(256) void gemm_feats_kernel(
    const float* __restrict__ X, const float* __restrict__ W)
{
    const int BM = 64, BN = 64, BK = 16;
    __shared__ float As[BK][BM];   // transposed X tile
    __shared__ float Bs[BK][BN];

    const int m0 = blockIdx.y * BM;
    const int c0 = blockIdx.x * BN;
    const int h0 = c0 >> 7;        // tile never straddles a head (64 | 128)
    const int o0 = c0 & 127;
    const float* __restrict__ Wb = W + h0 * (F_IN * FO_DIM) + o0;

    const int tid = threadIdx.x;
    const int tx = tid & 15, ty = tid >> 4;

    const int ar = tid >> 2;          // 0..63 (row in X tile)
    const int ac = (tid & 3) * 4;     // 0,4,8,12 (k within tile)
    const int br = tid >> 4;          // 0..15 (k row in W tile)
    const int bc = (tid & 15) * 4;    // 0..60

    float acc[4][4];
    #pragma unroll
    for (int i = 0; i < 4; i++)
        #pragma unroll
        for (int j = 0; j < 4; j++) acc[i][j] = 0.0f;

    for (int k0 = 0; k0 < F_IN; k0 += BK) {
        float4 xv = *(const float4*)&X[(m0 + ar) * F_IN + k0 + ac];
        As[ac + 0][ar] = xv.x;
        As[ac + 1][ar] = xv.y;
        As[ac + 2][ar] = xv.z;
        As[ac + 3][ar] = xv.w;
        float4 wv = *(const float4*)&Wb[(k0 + br) * FO_DIM + bc];
        *(float4*)&Bs[br][bc] = wv;
        __syncthreads();

        #pragma unroll
        for (int k = 0; k < BK; k++) {
            float4 a = *(const float4*)&As[k][ty * 4];
            float4 b = *(const float4*)&Bs[k][tx * 4];
            acc[0][0] = fmaf(a.x, b.x, acc[0][0]);
            acc[0][1] = fmaf(a.x, b.y, acc[0][1]);
            acc[0][2] = fmaf(a.x, b.z, acc[0][2]);
            acc[0][3] = fmaf(a.x, b.w, acc[0][3]);
            acc[1][0] = fmaf(a.y, b.x, acc[1][0]);
            acc[1][1] = fmaf(a.y, b.y, acc[1][1]);
            acc[1][2] = fmaf(a.y, b.z, acc[1][2]);
            acc[1][3] = fmaf(a.y, b.w, acc[1][3]);
            acc[2][0] = fmaf(a.z, b.x, acc[2][0]);
            acc[2][1] = fmaf(a.z, b.y, acc[2][1]);
            acc[2][2] = fmaf(a.z, b.z, acc[2][2]);
            acc[2][3] = fmaf(a.z, b.w, acc[2][3]);
            acc[3][0] = fmaf(a.w, b.x, acc[3][0]);
            acc[3][1] = fmaf(a.w, b.y, acc[3][1]);
            acc[3][2] = fmaf(a.w, b.z, acc[3][2]);
            acc[3][3] = fmaf(a.w, b.w, acc[3][3]);
        }
        __syncthreads();
    }

    #pragma unroll
    for (int i = 0; i < 4; i++) {
        float4 v = make_float4(acc[i][0], acc[i][1], acc[i][2], acc[i][3]);
        *(float4*)&g_feats[(m0 + ty * 4 + i) * C_OUT + c0 + tx * 4] = v;
    }
}

// ---------------------------------------------------------------------------
// Kernel 2: per-node, per-head attention scores.
// es[n,h] = feats[n, h*128: ] . a_self[h],  en likewise. 4 warps = 4 heads.
// ---------------------------------------------------------------------------
__global__ __launch_bounds__(128) void escore_kernel(
    const float* __restrict__ a_self, const float* __restrict__ a_neigh)
{
    const int n = blockIdx.x;
    const int h = threadIdx.x >> 5;
    const int lane = threadIdx.x & 31;
    const float* __restrict__ fr = g_feats + n * C_OUT + h * FO_DIM;
    const float* __restrict__ as = a_self + h * FO_DIM;
    const float* __restrict__ an = a_neigh + h * FO_DIM;
    float s = 0.f, e = 0.f;
    #pragma unroll
    for (int k = 0; k < FO_DIM; k += 32) {
        float f = fr[k + lane];
        s = fmaf(f, as[k + lane], s);
        e = fmaf(f, an[k + lane], e);
    }
    #pragma unroll
    for (int o = 16; o > 0; o >>= 1) {
        s += __shfl_xor_sync(0xffffffffu, s, o);
        e += __shfl_xor_sync(0xffffffffu, e, o);
    }
    if (lane == 0) {
        g_es[n * H_HEADS + h] = s;
        g_en[n * H_HEADS + h] = e;
    }
}

// ---------------------------------------------------------------------------
// Kernel 3: one block per destination node i.
//  - scan A[i,:] in chunks of 1024, ordered prefix-sum compaction
//  - online softmax per head (deterministic, exact match: masked exp == 0)
//  - gather-aggregate feats rows (hits L2)
// ---------------------------------------------------------------------------
#define CHUNK 1024

__global__ __launch_bounds__(256) void attn_agg_kernel(
    const float* __restrict__ A, const float* __restrict__ bias,
    float* __restrict__ out)
{
    __shared__ int   sidx[CHUNK];
    __shared__ float sl[H_HEADS][CHUNK];   // logits, then exp weights (in-place)
    __shared__ float red[8][H_HEADS];
    __shared__ float cred[H_HEADS];        // chunk max, then chunk sum
    __shared__ int   warp_tot[8];

    const int i = blockIdx.x;
    const int t = threadIdx.x;
    const int lane = t & 31, wid = t >> 5;
    const int col0 = t, col1 = t + 256;
    const int h0 = col0 >> 7, h1 = col1 >> 7;

    float esi[H_HEADS];
    #pragma unroll
    for (int h = 0; h < H_HEADS; h++) esi[h] = g_es[i * H_HEADS + h];

    float m_run[H_HEADS], s_run[H_HEADS];
    #pragma unroll
    for (int h = 0; h < H_HEADS; h++) { m_run[h] = -1e30f; s_run[h] = 0.f; }
    float acc0 = 0.f, acc1 = 0.f;

    const float* __restrict__ Arow = A + (size_t)i * N_NODES;

    for (int cb = 0; cb < N_NODES; cb += CHUNK) {
        // ---- ordered compaction of nonzero columns ----
        float4 av = *(const float4*)&Arow[cb + t * 4];
        int c4 = (av.x != 0.f) + (av.y != 0.f) + (av.z != 0.f) + (av.w != 0.f);
        int incl = c4;
        #pragma unroll
        for (int o = 1; o < 32; o <<= 1) {
            int v = __shfl_up_sync(0xffffffffu, incl, o);
            if (lane >= o) incl += v;
        }
        if (lane == 31) warp_tot[wid] = incl;
        __syncthreads();
        int wbase = 0, tot = 0;
        #pragma unroll
        for (int w2 = 0; w2 < 8; w2++) {
            int v = warp_tot[w2];
            if (w2 < wid) wbase += v;
            tot += v;
        }
        int pos = wbase + (incl - c4);
        int base_j = cb + t * 4;
        if (av.x != 0.f) sidx[pos++] = base_j + 0;
        if (av.y != 0.f) sidx[pos++] = base_j + 1;
        if (av.z != 0.f) sidx[pos++] = base_j + 2;
        if (av.w != 0.f) sidx[pos++] = base_j + 3;
        __syncthreads();
        const int cnt = tot;
        if (cnt == 0) continue;    // uniform across block

        // ---- logits + chunk max ----
        float lm[H_HEADS];
        #pragma unroll
        for (int h = 0; h < H_HEADS; h++) lm[h] = -1e30f;
        for (int nn = t; nn < cnt; nn += 256) {
            int j = sidx[nn];
            float4 e4 = *(const float4*)&g_en[j * 4];
            float l0 = esi[0] + e4.x; l0 = l0 > 0.f ? l0 : 0.2f * l0;
            float l1 = esi[1] + e4.y; l1 = l1 > 0.f ? l1 : 0.2f * l1;
            float l2 = esi[2] + e4.z; l2 = l2 > 0.f ? l2 : 0.2f * l2;
            float l3 = esi[3] + e4.w; l3 = l3 > 0.f ? l3 : 0.2f * l3;
            sl[0][nn] = l0; sl[1][nn] = l1; sl[2][nn] = l2; sl[3][nn] = l3;
            lm[0] = fmaxf(lm[0], l0); lm[1] = fmaxf(lm[1], l1);
            lm[2] = fmaxf(lm[2], l2); lm[3] = fmaxf(lm[3], l3);
        }
        #pragma unroll
        for (int o = 16; o > 0; o >>= 1)
            #pragma unroll
            for (int h = 0; h < H_HEADS; h++)
                lm[h] = fmaxf(lm[h], __shfl_xor_sync(0xffffffffu, lm[h], o));
        if (lane == 0)
            #pragma unroll
            for (int h = 0; h < H_HEADS; h++) red[wid][h] = lm[h];
        __syncthreads();
        if (t < H_HEADS) {
            float r = red[0][t];
            #pragma unroll
            for (int w2 = 1; w2 < 8; w2++) r = fmaxf(r, red[w2][t]);
            cred[t] = r;
        }
        __syncthreads();
        float m_new[H_HEADS];
        #pragma unroll
        for (int h = 0; h < H_HEADS; h++) m_new[h] = fmaxf(m_run[h], cred[h]);
        __syncthreads();

        // ---- exp + chunk sum (in-place weights) ----
        float ls[H_HEADS];
        #pragma unroll
        for (int h = 0; h < H_HEADS; h++) ls[h] = 0.f;
        for (int nn = t; nn < cnt; nn += 256) {
            #pragma unroll
            for (int h = 0; h < H_HEADS; h++) {
                float w = __expf(sl[h][nn] - m_new[h]);
                sl[h][nn] = w;
                ls[h] += w;
            }
        }
        #pragma unroll
        for (int o = 16; o > 0; o >>= 1)
            #pragma unroll
            for (int h = 0; h < H_HEADS; h++)
                ls[h] += __shfl_xor_sync(0xffffffffu, ls[h], o);
        if (lane == 0)
            #pragma unroll
            for (int h = 0; h < H_HEADS; h++) red[wid][h] = ls[h];
        __syncthreads();
        if (t < H_HEADS) {
            float r = red[0][t];
            #pragma unroll
            for (int w2 = 1; w2 < 8; w2++) r += red[w2][t];
            cred[t] = r;
        }
        __syncthreads();

        float rr[H_HEADS];
        #pragma unroll
        for (int h = 0; h < H_HEADS; h++) {
            rr[h] = __expf(m_run[h] - m_new[h]);
            s_run[h] = s_run[h] * rr[h] + cred[h];
            m_run[h] = m_new[h];
        }
        acc0 *= rr[h0];
        acc1 *= rr[h1];

        // ---- gather-aggregate (L2 hits on g_feats) ----
        #pragma unroll 4
        for (int nn = 0; nn < cnt; nn++) {
            float w0 = sl[h0][nn];
            float w1 = sl[h1][nn];
            const float* __restrict__ fr = g_feats + sidx[nn] * C_OUT;
            acc0 = fmaf(w0, fr[col0], acc0);
            acc1 = fmaf(w1, fr[col1], acc1);
        }
    }

    float o0 = acc0 / s_run[h0] + bias[col0];
    float o1 = acc1 / s_run[h1] + bias[col1];
    out[(size_t)i * C_OUT + col0] = fmaxf(o0, 0.f);
    out[(size_t)i * C_OUT + col1] = fmaxf(o1, 0.f);
}

// ---------------------------------------------------------------------------
extern "C" void kernel_launch(void* const* d_in, const int* in_sizes, int n_in,
                              void* d_out, int out_size)
{
    const float* X       = (const float*)d_in[0];
    const float* A       = (const float*)d_in[1];
    const float* W       = (const float*)d_in[2];
    const float* b       = (const float*)d_in[3];
    const float* a_self  = (const float*)d_in[4];
    const float* a_neigh = (const float*)d_in[5];
    float* out = (float*)d_out;

    dim3 g1(C_OUT / 64, N_NODES / 64);
    gemm_feats_kernel<<<g1, 256>>>(X, W);
    escore_kernel<<<N_NODES, 128>>>(a_self, a_neigh);
    attn_agg_kernel<<<N_NODES, 256>>>(A, b, out);
    (void)in_sizes; (void)n_in; (void)out_size;
}

// round 3
// speedup vs baseline: 1.5698x; 1.5698x over previous
#include <cuda_runtime.h>
#include <cuda_bf16.h>
#include <cstdint>

#define N_NODES 4096
#define F_IN    512
#define H_HEADS 4
#define FO_DIM  128
#define C_OUT   512   // H_HEADS * FO_DIM
#define MAXN    512   // neighbor cap (binomial(4096,.01): max ~70, huge margin)

// ---------------- device scratch (allocation-free rule) ----------------
__device__ float         g_feats[N_NODES * C_OUT];   // fp32 features, node-major (8 MB)
__device__ float         g_es[N_NODES * H_HEADS];
__device__ float         g_en[N_NODES * H_HEADS];
__device__ __nv_bfloat16 g_xhi[N_NODES * F_IN];      // X split: hi
__device__ __nv_bfloat16 g_xlo[N_NODES * F_IN];      //          lo
__device__ __nv_bfloat16 g_whi[C_OUT * F_IN];        // W^T (K-major [c][f]) split: hi
__device__ __nv_bfloat16 g_wlo[C_OUT * F_IN];        //                              lo

// ---------------------------------------------------------------------------
// Conversion kernels: fp32 -> bf16 hi/lo split
// ---------------------------------------------------------------------------
__global__ __launch_bounds__(256) void convx_kernel(const float* __restrict__ X) {
    int i = blockIdx.x * 256 + threadIdx.x;
    float x = X[i];
    __nv_bfloat16 hi = __float2bfloat16(x);
    g_xhi[i] = hi;
    g_xlo[i] = __float2bfloat16(x - __bfloat162float(hi));
}

// W [H][F][FO] -> W^T K-major [c = h*128+o][f], split hi/lo.  32x32 smem transpose.
__global__ __launch_bounds__(256) void convw_kernel(const float* __restrict__ W) {
    __shared__ float tile[32][33];
    const int h = blockIdx.z;
    const int f0 = blockIdx.x * 32, o0 = blockIdx.y * 32;
    const int tx = threadIdx.x & 31, ty0 = threadIdx.x >> 5;   // 32 x 8
    #pragma unroll
    for (int r = 0; r < 4; r++) {
        int ty = ty0 + r * 8;
        tile[ty][tx] = W[((size_t)h * F_IN + f0 + ty) * FO_DIM + o0 + tx];
    }
    __syncthreads();
    #pragma unroll
    for (int r = 0; r < 4; r++) {
        int ty = ty0 + r * 8;
        float v = tile[tx][ty];                    // v = W[h][f0+tx][o0+ty]
        __nv_bfloat16 hi = __float2bfloat16(v);
        size_t dst = (size_t)(h * FO_DIM + o0 + ty) * F_IN + f0 + tx;
        g_whi[dst] = hi;
        g_wlo[dst] = __float2bfloat16(v - __bfloat162float(hi));
    }
}

// ---------------------------------------------------------------------------
// Kernel 1: warp-level HMMA bf16 split-3 GEMM (arch-neutral mma.sync):
//   feats = X @ W^T, fp32 accum, 3 products (hi*hi + hi*lo + lo*hi).
// CTA tile 128x128, 8 warps (4x2), warp tile 32x64, K chunk 32.
// ---------------------------------------------------------------------------
#define SPAD 40   // smem row stride in bf16 (32 data + 8 pad) -> conflict-free frags

__device__ __forceinline__ void mma16816(float* c, const uint32_t* a, const uint32_t* b) {
    asm volatile("mma.sync.aligned.m16n8k16.row.col.f32.bf16.bf16.f32 "
                 "{%0,%1,%2,%3}, {%4,%5,%6,%7}, {%8,%9}, {%0,%1,%2,%3};"
                 : "+f"(c[0]), "+f"(c[1]), "+f"(c[2]), "+f"(c[3])
                 : "r"(a[0]), "r"(a[1]), "r"(a[2]), "r"(a[3]),
                   "r"(b[0]), "r"(b[1]));
}

__device__ __forceinline__ void ld_tile(__nv_bfloat16 (*dst)[SPAD],
                                        const __nv_bfloat16* __restrict__ src,
                                        int row0, int k0, int tid) {
    #pragma unroll
    for (int i = 0; i < 2; i++) {
        int u = tid * 2 + i;          // 0..511 units of 16B (128 rows x 4 units)
        int r = u >> 2, q = u & 3;
        *(uint4*)&dst[r][q * 8] = *(const uint4*)&src[(size_t)(row0 + r) * F_IN + k0 + q * 8];
    }
}

__global__ __launch_bounds__(256) void gemm_mma_kernel() {
    __shared__ __nv_bfloat16 Ahi[128][SPAD], Alo[128][SPAD];
    __shared__ __nv_bfloat16 Bhi[128][SPAD], Blo[128][SPAD];

    const int tid  = threadIdx.x;
    const int wid  = tid >> 5, lane = tid & 31;
    const int gid  = lane >> 2;           // 0..7
    const int qid  = lane & 3;            // 0..3
    const int wm   = (wid & 3) * 32;      // warp m offset in CTA tile
    const int wn   = (wid >> 2) * 64;     // warp n offset in CTA tile

    const int n0 = blockIdx.x * 128;
    const int m0 = blockIdx.y * 128;

    float acc[2][8][4];
    #pragma unroll
    for (int mt = 0; mt < 2; mt++)
        #pragma unroll
        for (int nt = 0; nt < 8; nt++)
            #pragma unroll
            for (int r = 0; r < 4; r++) acc[mt][nt][r] = 0.f;

    for (int kc = 0; kc < F_IN; kc += 32) {
        __syncthreads();
        ld_tile(Ahi, g_xhi, m0, kc, tid);
        ld_tile(Alo, g_xlo, m0, kc, tid);
        ld_tile(Bhi, g_whi, n0, kc, tid);
        ld_tile(Blo, g_wlo, n0, kc, tid);
        __syncthreads();

        #pragma unroll
        for (int ks = 0; ks < 32; ks += 16) {
            // A fragments: 2 m16 tiles, hi + lo
            uint32_t ah[2][4], al[2][4];
            #pragma unroll
            for (int mt = 0; mt < 2; mt++) {
                int r0 = wm + mt * 16 + gid;
                int kp = ks + qid * 2;
                ah[mt][0] = *(const uint32_t*)&Ahi[r0][kp];
                ah[mt][1] = *(const uint32_t*)&Ahi[r0 + 8][kp];
                ah[mt][2] = *(const uint32_t*)&Ahi[r0][kp + 8];
                ah[mt][3] = *(const uint32_t*)&Ahi[r0 + 8][kp + 8];
                al[mt][0] = *(const uint32_t*)&Alo[r0][kp];
                al[mt][1] = *(const uint32_t*)&Alo[r0 + 8][kp];
                al[mt][2] = *(const uint32_t*)&Alo[r0][kp + 8];
                al[mt][3] = *(const uint32_t*)&Alo[r0 + 8][kp + 8];
            }
            #pragma unroll
            for (int nt = 0; nt < 8; nt++) {
                int nr = wn + nt * 8 + gid;
                int kp = ks + qid * 2;
                uint32_t bh[2], bl[2];
                bh[0] = *(const uint32_t*)&Bhi[nr][kp];
                bh[1] = *(const uint32_t*)&Bhi[nr][kp + 8];
                bl[0] = *(const uint32_t*)&Blo[nr][kp];
                bl[1] = *(const uint32_t*)&Blo[nr][kp + 8];
                #pragma unroll
                for (int mt = 0; mt < 2; mt++) {
                    mma16816(acc[mt][nt], ah[mt], bh);   // hi*hi
                    mma16816(acc[mt][nt], ah[mt], bl);   // hi*lo
                    mma16816(acc[mt][nt], al[mt], bh);   // lo*hi
                }
            }
        }
    }

    // Epilogue: D rows gid/gid+8 per m16 tile, col pairs qid*2
    #pragma unroll
    for (int mt = 0; mt < 2; mt++) {
        #pragma unroll
        for (int nt = 0; nt < 8; nt++) {
            int row = m0 + wm + mt * 16 + gid;
            int col = n0 + wn + nt * 8 + qid * 2;
            *(float2*)&g_feats[(size_t)row * C_OUT + col] =
                make_float2(acc[mt][nt][0], acc[mt][nt][1]);
            *(float2*)&g_feats[(size_t)(row + 8) * C_OUT + col] =
                make_float2(acc[mt][nt][2], acc[mt][nt][3]);
        }
    }
}

// ---------------------------------------------------------------------------
// Kernel 2: per-node per-head scores (fp32, from fp32 feats)
// ---------------------------------------------------------------------------
__global__ __launch_bounds__(128) void escore_kernel(
    const float* __restrict__ a_self, const float* __restrict__ a_neigh)
{
    const int n = blockIdx.x;
    const int h = threadIdx.x >> 5;
    const int lane = threadIdx.x & 31;
    const float* __restrict__ fr = g_feats + (size_t)n * C_OUT + h * FO_DIM;
    const float* __restrict__ as = a_self + h * FO_DIM;
    const float* __restrict__ an = a_neigh + h * FO_DIM;
    float s = 0.f, e = 0.f;
    #pragma unroll
    for (int k = 0; k < FO_DIM; k += 32) {
        float f = fr[k + lane];
        s = fmaf(f, as[k + lane], s);
        e = fmaf(f, an[k + lane], e);
    }
    #pragma unroll
    for (int o = 16; o > 0; o >>= 1) {
        s += __shfl_xor_sync(0xffffffffu, s, o);
        e += __shfl_xor_sync(0xffffffffu, e, o);
    }
    if (lane == 0) {
        g_es[n * H_HEADS + h] = s;
        g_en[n * H_HEADS + h] = e;
    }
}

// ---------------------------------------------------------------------------
// Kernel 3: per-node block. Full neighbor list in smem (<=512), single-pass
// softmax (no online rescale), then L2 gather-aggregate.
// ---------------------------------------------------------------------------
__global__ __launch_bounds__(256) void attn_agg_kernel(
    const float* __restrict__ A, const float* __restrict__ bias,
    float* __restrict__ out)
{
    __shared__ int   sidx[MAXN];
    __shared__ float sw[H_HEADS][MAXN];
    __shared__ float red[8][H_HEADS];
    __shared__ int   warp_tot[8];

    const int i = blockIdx.x;
    const int t = threadIdx.x;
    const int lane = t & 31, wid = t >> 5;
    const int col0 = t, col1 = t + 256;
    const int h0 = col0 >> 7, h1 = col1 >> 7;

    const float* __restrict__ Arow = A + (size_t)i * N_NODES;

    // ---- compaction of nonzero columns into sidx[0..cnt) ----
    int base = 0;
    for (int cb = 0; cb < N_NODES; cb += 1024) {
        float4 av = *(const float4*)&Arow[cb + t * 4];
        int c4 = (av.x != 0.f) + (av.y != 0.f) + (av.z != 0.f) + (av.w != 0.f);
        int incl = c4;
        #pragma unroll
        for (int o = 1; o < 32; o <<= 1) {
            int v = __shfl_up_sync(0xffffffffu, incl, o);
            if (lane >= o) incl += v;
        }
        __syncthreads();                 // protect warp_tot from previous iter readers
        if (lane == 31) warp_tot[wid] = incl;
        __syncthreads();
        int wbase = 0, tot = 0;
        #pragma unroll
        for (int w2 = 0; w2 < 8; w2++) {
            int v = warp_tot[w2];
            if (w2 < wid) wbase += v;
            tot += v;
        }
        int pos = base + wbase + (incl - c4);
        int bj = cb + t * 4;
        if (av.x != 0.f && pos < MAXN) sidx[pos++] = bj + 0;
        if (av.y != 0.f && pos < MAXN) sidx[pos++] = bj + 1;
        if (av.z != 0.f && pos < MAXN) sidx[pos++] = bj + 2;
        if (av.w != 0.f && pos < MAXN) sidx[pos++] = bj + 3;
        base += tot;
    }
    const int cnt = base < MAXN ? base : MAXN;
    __syncthreads();

    // ---- logits + block max per head ----
    float esi[H_HEADS];
    #pragma unroll
    for (int h = 0; h < H_HEADS; h++) esi[h] = g_es[i * H_HEADS + h];

    float lm[H_HEADS];
    #pragma unroll
    for (int h = 0; h < H_HEADS; h++) lm[h] = -1e30f;
    for (int nn = t; nn < cnt; nn += 256) {
        int j = sidx[nn];
        float4 e4 = *(const float4*)&g_en[j * 4];
        float l0 = esi[0] + e4.x; l0 = l0 > 0.f ? l0 : 0.2f * l0;
        float l1 = esi[1] + e4.y; l1 = l1 > 0.f ? l1 : 0.2f * l1;
        float l2 = esi[2] + e4.z; l2 = l2 > 0.f ? l2 : 0.2f * l2;
        float l3 = esi[3] + e4.w; l3 = l3 > 0.f ? l3 : 0.2f * l3;
        sw[0][nn] = l0; sw[1][nn] = l1; sw[2][nn] = l2; sw[3][nn] = l3;
        lm[0] = fmaxf(lm[0], l0); lm[1] = fmaxf(lm[1], l1);
        lm[2] = fmaxf(lm[2], l2); lm[3] = fmaxf(lm[3], l3);
    }
    #pragma unroll
    for (int o = 16; o > 0; o >>= 1)
        #pragma unroll
        for (int h = 0; h < H_HEADS; h++)
            lm[h] = fmaxf(lm[h], __shfl_xor_sync(0xffffffffu, lm[h], o));
    if (lane == 0)
        #pragma unroll
        for (int h = 0; h < H_HEADS; h++) red[wid][h] = lm[h];
    __syncthreads();
    float mx[H_HEADS];
    #pragma unroll
    for (int h = 0; h < H_HEADS; h++) {
        float r = red[0][h];
        #pragma unroll
        for (int w2 = 1; w2 < 8; w2++) r = fmaxf(r, red[w2][h]);
        mx[h] = r;
    }
    __syncthreads();

    // ---- exp + block sum per head (weights in-place in smem) ----
    float ls[H_HEADS];
    #pragma unroll
    for (int h = 0; h < H_HEADS; h++) ls[h] = 0.f;
    for (int nn = t; nn < cnt; nn += 256) {
        #pragma unroll
        for (int h = 0; h < H_HEADS; h++) {
            float w = __expf(sw[h][nn] - mx[h]);
            sw[h][nn] = w;
            ls[h] += w;
        }
    }
    #pragma unroll
    for (int o = 16; o > 0; o >>= 1)
        #pragma unroll
        for (int h = 0; h < H_HEADS; h++)
            ls[h] += __shfl_xor_sync(0xffffffffu, ls[h], o);
    if (lane == 0)
        #pragma unroll
        for (int h = 0; h < H_HEADS; h++) red[wid][h] = ls[h];
    __syncthreads();
    float sum0 = 0.f, sum1 = 0.f;
    {
        float s0 = 0.f, s1 = 0.f;
        #pragma unroll
        for (int w2 = 0; w2 < 8; w2++) { s0 += red[w2][h0]; s1 += red[w2][h1]; }
        sum0 = s0; sum1 = s1;
    }

    // ---- gather-aggregate (g_feats resident in L2) ----
    float acc0 = 0.f, acc1 = 0.f;
    #pragma unroll 4
    for (int nn = 0; nn < cnt; nn++) {
        float w0 = sw[h0][nn];
        float w1 = sw[h1][nn];
        const float* __restrict__ fr = g_feats + (size_t)sidx[nn] * C_OUT;
        acc0 = fmaf(w0, fr[col0], acc0);
        acc1 = fmaf(w1, fr[col1], acc1);
    }

    float o0 = acc0 / sum0 + bias[col0];
    float o1 = acc1 / sum1 + bias[col1];
    out[(size_t)i * C_OUT + col0] = fmaxf(o0, 0.f);
    out[(size_t)i * C_OUT + col1] = fmaxf(o1, 0.f);
}

// ---------------------------------------------------------------------------
extern "C" void kernel_launch(void* const* d_in, const int* in_sizes, int n_in,
                              void* d_out, int out_size)
{
    const float* X       = (const float*)d_in[0];
    const float* A       = (const float*)d_in[1];
    const float* W       = (const float*)d_in[2];
    const float* b       = (const float*)d_in[3];
    const float* a_self  = (const float*)d_in[4];
    const float* a_neigh = (const float*)d_in[5];
    float* out = (float*)d_out;

    convx_kernel<<<(N_NODES * F_IN) / 256, 256>>>(X);
    convw_kernel<<<dim3(F_IN / 32, FO_DIM / 32, H_HEADS), 256>>>(W);
    gemm_mma_kernel<<<dim3(C_OUT / 128, N_NODES / 128), 256>>>();
    escore_kernel<<<N_NODES, 128>>>(a_self, a_neigh);
    attn_agg_kernel<<<N_NODES, 256>>>(A, b, out);
    (void)in_sizes; (void)n_in; (void)out_size;
}

// round 4
// speedup vs baseline: 1.9178x; 1.2217x over previous
#include <cuda_runtime.h>
#include <cuda_bf16.h>
#include <cuda_fp16.h>
#include <cstdint>

#define N_NODES 4096
#define F_IN    512
#define H_HEADS 4
#define FO_DIM  128
#define C_OUT   512   // H_HEADS * FO_DIM
#define MAXN    512   // neighbor cap (binomial(4096,.01): max ~70, huge margin)

// ---------------- device scratch (allocation-free rule) ----------------
__device__ __half        g_feats_h[N_NODES * C_OUT]; // fp16 features, node-major (4 MB)
__device__ float         g_es[N_NODES * H_HEADS];
__device__ float         g_en[N_NODES * H_HEADS];
__device__ __nv_bfloat16 g_xhi[N_NODES * F_IN];      // X split: hi
__device__ __nv_bfloat16 g_xlo[N_NODES * F_IN];      //          lo
__device__ __nv_bfloat16 g_whi[C_OUT * F_IN];        // W^T (K-major [c][f]) split: hi
__device__ __nv_bfloat16 g_wlo[C_OUT * F_IN];        //                              lo

// ---------------------------------------------------------------------------
// Conversion kernels: fp32 -> bf16 hi/lo split
// ---------------------------------------------------------------------------
__global__ __launch_bounds__(256) void convx_kernel(const float* __restrict__ X) {
    int i = blockIdx.x * 256 + threadIdx.x;
    float x = X[i];
    __nv_bfloat16 hi = __float2bfloat16(x);
    g_xhi[i] = hi;
    g_xlo[i] = __float2bfloat16(x - __bfloat162float(hi));
}

// W [H][F][FO] -> W^T K-major [c = h*128+o][f], split hi/lo.  32x32 smem transpose.
__global__ __launch_bounds__(256) void convw_kernel(const float* __restrict__ W) {
    __shared__ float tile[32][33];
    const int h = blockIdx.z;
    const int f0 = blockIdx.x * 32, o0 = blockIdx.y * 32;
    const int tx = threadIdx.x & 31, ty0 = threadIdx.x >> 5;   // 32 x 8
    #pragma unroll
    for (int r = 0; r < 4; r++) {
        int ty = ty0 + r * 8;
        tile[ty][tx] = W[((size_t)h * F_IN + f0 + ty) * FO_DIM + o0 + tx];
    }
    __syncthreads();
    #pragma unroll
    for (int r = 0; r < 4; r++) {
        int ty = ty0 + r * 8;
        float v = tile[tx][ty];                    // v = W[h][f0+tx][o0+ty]
        __nv_bfloat16 hi = __float2bfloat16(v);
        size_t dst = (size_t)(h * FO_DIM + o0 + ty) * F_IN + f0 + tx;
        g_whi[dst] = hi;
        g_wlo[dst] = __float2bfloat16(v - __bfloat162float(hi));
    }
}

// ---------------------------------------------------------------------------
// Kernel 1: HMMA bf16 split-3 GEMM with cp.async double buffering.
// Fused epilogue: fp16 feats store + per-head es/en dot reduction.
// CTA tile 128x128 (tile cols == one full head), 8 warps (4m x 2n),
// warp tile 32x64, K chunk 32, 2 smem stages.
// ---------------------------------------------------------------------------
#define SPAD 40                       // bf16 row stride (32 data + 8 pad)
#define TILE_B   (128 * SPAD * 2)     // 10240 bytes per tile
#define STAGE_B  (4 * TILE_B)         // 40960 bytes per stage
#define GEMM_SMEM (2 * STAGE_B)       // 81920 bytes

__device__ __forceinline__ void mma16816(float* c, const uint32_t* a, const uint32_t* b) {
    asm volatile("mma.sync.aligned.m16n8k16.row.col.f32.bf16.bf16.f32 "
                 "{%0,%1,%2,%3}, {%4,%5,%6,%7}, {%8,%9}, {%0,%1,%2,%3};"
                 : "+f"(c[0]), "+f"(c[1]), "+f"(c[2]), "+f"(c[3])
                 : "r"(a[0]), "r"(a[1]), "r"(a[2]), "r"(a[3]),
                   "r"(b[0]), "r"(b[1]));
}
__device__ __forceinline__ void cpa16(uint32_t dst, const void* src) {
    asm volatile("cp.async.cg.shared.global [%0], [%1], 16;" :: "r"(dst), "l"(src));
}
__device__ __forceinline__ uint32_t smem_u32(const void* p) {
    uint32_t a;
    asm("{ .reg .u64 t; cvta.to.shared.u64 t, %1; cvt.u32.u64 %0, t; }" : "=r"(a) : "l"(p));
    return a;
}

__device__ __forceinline__ void issue_tile(uint32_t sdst, const __nv_bfloat16* __restrict__ src,
                                           int row0, int k0, int tid) {
    #pragma unroll
    for (int i = 0; i < 2; i++) {
        int u = tid * 2 + i;          // 512 units of 16B: 128 rows x 4
        int r = u >> 2, q = u & 3;
        cpa16(sdst + (uint32_t)(r * (SPAD * 2) + q * 16),
              src + (size_t)(row0 + r) * F_IN + k0 + q * 8);
    }
}

__global__ __launch_bounds__(256) void gemm_mma_kernel(
    const float* __restrict__ a_self, const float* __restrict__ a_neigh)
{
    extern __shared__ __align__(16) char smem[];
    const uint32_t sb = smem_u32(smem);

    const int tid  = threadIdx.x;
    const int wid  = tid >> 5, lane = tid & 31;
    const int gid  = lane >> 2;           // 0..7
    const int qid  = lane & 3;            // 0..3
    const int wm   = (wid & 3) * 32;      // warp m offset
    const int wn   = (wid >> 2) * 64;     // warp n offset

    const int n0 = blockIdx.x * 128;      // == head * 128
    const int m0 = blockIdx.y * 128;
    const int h  = blockIdx.x;

    float acc[2][8][4];
    #pragma unroll
    for (int mt = 0; mt < 2; mt++)
        #pragma unroll
        for (int nt = 0; nt < 8; nt++)
            #pragma unroll
            for (int r = 0; r < 4; r++) acc[mt][nt][r] = 0.f;

    const int NK = F_IN / 32;             // 16 chunks

    // prologue: stage 0
    {
        uint32_t st = sb;
        issue_tile(st,              g_xhi, m0, 0, tid);
        issue_tile(st + TILE_B,     g_xlo, m0, 0, tid);
        issue_tile(st + 2 * TILE_B, g_whi, n0, 0, tid);
        issue_tile(st + 3 * TILE_B, g_wlo, n0, 0, tid);
        asm volatile("cp.async.commit_group;" ::: "memory");
    }

    for (int kc = 0; kc < NK; kc++) {
        if (kc + 1 < NK) {
            uint32_t st = sb + ((kc + 1) & 1) * STAGE_B;
            int k0 = (kc + 1) * 32;
            issue_tile(st,              g_xhi, m0, k0, tid);
            issue_tile(st + TILE_B,     g_xlo, m0, k0, tid);
            issue_tile(st + 2 * TILE_B, g_whi, n0, k0, tid);
            issue_tile(st + 3 * TILE_B, g_wlo, n0, k0, tid);
            asm volatile("cp.async.commit_group;" ::: "memory");
            asm volatile("cp.async.wait_group 1;" ::: "memory");
        } else {
            asm volatile("cp.async.wait_group 0;" ::: "memory");
        }
        __syncthreads();

        char* stc = smem + (kc & 1) * STAGE_B;
        __nv_bfloat16 (*Ahi)[SPAD] = (__nv_bfloat16(*)[SPAD])(stc);
        __nv_bfloat16 (*Alo)[SPAD] = (__nv_bfloat16(*)[SPAD])(stc + TILE_B);
        __nv_bfloat16 (*Bhi)[SPAD] = (__nv_bfloat16(*)[SPAD])(stc + 2 * TILE_B);
        __nv_bfloat16 (*Blo)[SPAD] = (__nv_bfloat16(*)[SPAD])(stc + 3 * TILE_B);

        #pragma unroll
        for (int ks = 0; ks < 32; ks += 16) {
            uint32_t ah[2][4], al[2][4];
            #pragma unroll
            for (int mt = 0; mt < 2; mt++) {
                int r0 = wm + mt * 16 + gid;
                int kp = ks + qid * 2;
                ah[mt][0] = *(const uint32_t*)&Ahi[r0][kp];
                ah[mt][1] = *(const uint32_t*)&Ahi[r0 + 8][kp];
                ah[mt][2] = *(const uint32_t*)&Ahi[r0][kp + 8];
                ah[mt][3] = *(const uint32_t*)&Ahi[r0 + 8][kp + 8];
                al[mt][0] = *(const uint32_t*)&Alo[r0][kp];
                al[mt][1] = *(const uint32_t*)&Alo[r0 + 8][kp];
                al[mt][2] = *(const uint32_t*)&Alo[r0][kp + 8];
                al[mt][3] = *(const uint32_t*)&Alo[r0 + 8][kp + 8];
            }
            #pragma unroll
            for (int nt = 0; nt < 8; nt++) {
                int nr = wn + nt * 8 + gid;
                int kp = ks + qid * 2;
                uint32_t bh[2], bl[2];
                bh[0] = *(const uint32_t*)&Bhi[nr][kp];
                bh[1] = *(const uint32_t*)&Bhi[nr][kp + 8];
                bl[0] = *(const uint32_t*)&Blo[nr][kp];
                bl[1] = *(const uint32_t*)&Blo[nr][kp + 8];
                #pragma unroll
                for (int mt = 0; mt < 2; mt++) {
                    mma16816(acc[mt][nt], ah[mt], bh);   // hi*hi
                    mma16816(acc[mt][nt], ah[mt], bl);   // hi*lo
                    mma16816(acc[mt][nt], al[mt], bh);   // lo*hi
                }
            }
        }
        __syncthreads();
    }

    // ---------------- fused epilogue ----------------
    // 1) store fp16 feats, 2) per-thread partial es/en dots over owned cols
    const float* __restrict__ as = a_self + h * FO_DIM;
    const float* __restrict__ an = a_neigh + h * FO_DIM;
    float esp[4] = {0.f, 0.f, 0.f, 0.f};   // rows: mt*2 + {gid, gid+8}
    float enp[4] = {0.f, 0.f, 0.f, 0.f};

    #pragma unroll
    for (int nt = 0; nt < 8; nt++) {
        int col = wn + nt * 8 + qid * 2;
        float as0 = as[col], as1 = as[col + 1];
        float an0 = an[col], an1 = an[col + 1];
        #pragma unroll
        for (int mt = 0; mt < 2; mt++) {
            int row = m0 + wm + mt * 16 + gid;
            float c0 = acc[mt][nt][0], c1 = acc[mt][nt][1];
            float c2 = acc[mt][nt][2], c3 = acc[mt][nt][3];
            *(__half2*)&g_feats_h[(size_t)row * C_OUT + n0 + col] =
                __floats2half2_rn(c0, c1);
            *(__half2*)&g_feats_h[(size_t)(row + 8) * C_OUT + n0 + col] =
                __floats2half2_rn(c2, c3);
            esp[mt * 2 + 0] += c0 * as0 + c1 * as1;
            esp[mt * 2 + 1] += c2 * as0 + c3 * as1;
            enp[mt * 2 + 0] += c0 * an0 + c1 * an1;
            enp[mt * 2 + 1] += c2 * an0 + c3 * an1;
        }
    }
    // reduce over qid (lanes sharing gid)
    #pragma unroll
    for (int o = 1; o <= 2; o <<= 1) {
        #pragma unroll
        for (int r = 0; r < 4; r++) {
            esp[r] += __shfl_xor_sync(0xffffffffu, esp[r], o);
            enp[r] += __shfl_xor_sync(0xffffffffu, enp[r], o);
        }
    }
    // combine the two n-warps via smem (deterministic two-phase)
    float* esr = (float*)smem;         // 128 floats
    float* enr = esr + 128;
    __syncthreads();                   // all MMA smem reads done (loop-end sync) — safe alias
    if (wid < 4 && qid == 0) {
        #pragma unroll
        for (int mt = 0; mt < 2; mt++) {
            int r0 = wm + mt * 16 + gid;
            esr[r0] = esp[mt * 2];     esr[r0 + 8] = esp[mt * 2 + 1];
            enr[r0] = enp[mt * 2];     enr[r0 + 8] = enp[mt * 2 + 1];
        }
    }
    __syncthreads();
    if (wid >= 4 && qid == 0) {
        #pragma unroll
        for (int mt = 0; mt < 2; mt++) {
            int r0 = wm + mt * 16 + gid;
            esr[r0] += esp[mt * 2];     esr[r0 + 8] += esp[mt * 2 + 1];
            enr[r0] += enp[mt * 2];     enr[r0 + 8] += enp[mt * 2 + 1];
        }
    }
    __syncthreads();
    if (tid < 128) {
        g_es[(size_t)(m0 + tid) * H_HEADS + h] = esr[tid];
        g_en[(size_t)(m0 + tid) * H_HEADS + h] = enr[tid];
    }
}

// ---------------------------------------------------------------------------
// Kernel 3: per-node block. Compaction -> single-pass softmax -> fp16 gather.
// Thread t owns columns 2t, 2t+1 (same head h = t>>6).
// ---------------------------------------------------------------------------
__global__ __launch_bounds__(256) void attn_agg_kernel(
    const float* __restrict__ A, const float* __restrict__ bias,
    float* __restrict__ out)
{
    __shared__ int   sidx[MAXN];
    __shared__ float sw[H_HEADS][MAXN];
    __shared__ float red[8][H_HEADS];
    __shared__ int   warp_tot[8];

    const int i = blockIdx.x;
    const int t = threadIdx.x;
    const int lane = t & 31, wid = t >> 5;
    const int h0 = t >> 6;

    const float* __restrict__ Arow = A + (size_t)i * N_NODES;

    // ---- compaction of nonzero columns into sidx[0..cnt) ----
    int base = 0;
    for (int cb = 0; cb < N_NODES; cb += 1024) {
        float4 av = *(const float4*)&Arow[cb + t * 4];
        int c4 = (av.x != 0.f) + (av.y != 0.f) + (av.z != 0.f) + (av.w != 0.f);
        int incl = c4;
        #pragma unroll
        for (int o = 1; o < 32; o <<= 1) {
            int v = __shfl_up_sync(0xffffffffu, incl, o);
            if (lane >= o) incl += v;
        }
        __syncthreads();
        if (lane == 31) warp_tot[wid] = incl;
        __syncthreads();
        int wbase = 0, tot = 0;
        #pragma unroll
        for (int w2 = 0; w2 < 8; w2++) {
            int v = warp_tot[w2];
            if (w2 < wid) wbase += v;
            tot += v;
        }
        int pos = base + wbase + (incl - c4);
        int bj = cb + t * 4;
        if (av.x != 0.f && pos < MAXN) sidx[pos++] = bj + 0;
        if (av.y != 0.f && pos < MAXN) sidx[pos++] = bj + 1;
        if (av.z != 0.f && pos < MAXN) sidx[pos++] = bj + 2;
        if (av.w != 0.f && pos < MAXN) sidx[pos++] = bj + 3;
        base += tot;
    }
    const int cnt = base < MAXN ? base : MAXN;
    __syncthreads();

    // ---- logits + block max per head ----
    float esi[H_HEADS];
    #pragma unroll
    for (int h = 0; h < H_HEADS; h++) esi[h] = g_es[i * H_HEADS + h];

    float lm[H_HEADS];
    #pragma unroll
    for (int h = 0; h < H_HEADS; h++) lm[h] = -1e30f;
    for (int nn = t; nn < cnt; nn += 256) {
        int j = sidx[nn];
        float4 e4 = *(const float4*)&g_en[j * 4];
        float l0 = esi[0] + e4.x; l0 = l0 > 0.f ? l0 : 0.2f * l0;
        float l1 = esi[1] + e4.y; l1 = l1 > 0.f ? l1 : 0.2f * l1;
        float l2 = esi[2] + e4.z; l2 = l2 > 0.f ? l2 : 0.2f * l2;
        float l3 = esi[3] + e4.w; l3 = l3 > 0.f ? l3 : 0.2f * l3;
        sw[0][nn] = l0; sw[1][nn] = l1; sw[2][nn] = l2; sw[3][nn] = l3;
        lm[0] = fmaxf(lm[0], l0); lm[1] = fmaxf(lm[1], l1);
        lm[2] = fmaxf(lm[2], l2); lm[3] = fmaxf(lm[3], l3);
    }
    #pragma unroll
    for (int o = 16; o > 0; o >>= 1)
        #pragma unroll
        for (int h = 0; h < H_HEADS; h++)
            lm[h] = fmaxf(lm[h], __shfl_xor_sync(0xffffffffu, lm[h], o));
    if (lane == 0)
        #pragma unroll
        for (int h = 0; h < H_HEADS; h++) red[wid][h] = lm[h];
    __syncthreads();
    float mx[H_HEADS];
    #pragma unroll
    for (int h = 0; h < H_HEADS; h++) {
        float r = red[0][h];
        #pragma unroll
        for (int w2 = 1; w2 < 8; w2++) r = fmaxf(r, red[w2][h]);
        mx[h] = r;
    }
    __syncthreads();

    // ---- exp + block sum per head ----
    float ls[H_HEADS];
    #pragma unroll
    for (int h = 0; h < H_HEADS; h++) ls[h] = 0.f;
    for (int nn = t; nn < cnt; nn += 256) {
        #pragma unroll
        for (int h = 0; h < H_HEADS; h++) {
            float w = __expf(sw[h][nn] - mx[h]);
            sw[h][nn] = w;
            ls[h] += w;
        }
    }
    #pragma unroll
    for (int o = 16; o > 0; o >>= 1)
        #pragma unroll
        for (int h = 0; h < H_HEADS; h++)
            ls[h] += __shfl_xor_sync(0xffffffffu, ls[h], o);
    if (lane == 0)
        #pragma unroll
        for (int h = 0; h < H_HEADS; h++) red[wid][h] = ls[h];
    __syncthreads();
    float sum0 = 0.f;
    #pragma unroll
    for (int w2 = 0; w2 < 8; w2++) sum0 += red[w2][h0];

    // ---- fp16 gather-aggregate (L2-resident g_feats_h) ----
    float acc0 = 0.f, acc1 = 0.f;
    #pragma unroll 4
    for (int nn = 0; nn < cnt; nn++) {
        float w = sw[h0][nn];
        const __half2* __restrict__ fr =
            (const __half2*)(g_feats_h + (size_t)sidx[nn] * C_OUT);
        float2 vf = __half22float2(fr[t]);
        acc0 = fmaf(w, vf.x, acc0);
        acc1 = fmaf(w, vf.y, acc1);
    }

    float inv = 1.0f / sum0;
    float o0 = acc0 * inv + bias[2 * t];
    float o1 = acc1 * inv + bias[2 * t + 1];
    *(float2*)&out[(size_t)i * C_OUT + 2 * t] =
        make_float2(fmaxf(o0, 0.f), fmaxf(o1, 0.f));
}

// ---------------------------------------------------------------------------
extern "C" void kernel_launch(void* const* d_in, const int* in_sizes, int n_in,
                              void* d_out, int out_size)
{
    const float* X       = (const float*)d_in[0];
    const float* A       = (const float*)d_in[1];
    const float* W       = (const float*)d_in[2];
    const float* b       = (const float*)d_in[3];
    const float* a_self  = (const float*)d_in[4];
    const float* a_neigh = (const float*)d_in[5];
    float* out = (float*)d_out;

    cudaFuncSetAttribute(gemm_mma_kernel,
                         cudaFuncAttributeMaxDynamicSharedMemorySize, GEMM_SMEM);

    convx_kernel<<<(N_NODES * F_IN) / 256, 256>>>(X);
    convw_kernel<<<dim3(F_IN / 32, FO_DIM / 32, H_HEADS), 256>>>(W);
    gemm_mma_kernel<<<dim3(C_OUT / 128, N_NODES / 128), 256, GEMM_SMEM>>>(a_self, a_neigh);
    attn_agg_kernel<<<N_NODES, 256>>>(A, b, out);
    (void)in_sizes; (void)n_in; (void)out_size;
}